// round 1
// baseline (speedup 1.0000x reference)
#include <cuda_runtime.h>
#include <math.h>

// Problem constants
constexpr int cB = 2;
constexpr int cS = 2048;
constexpr int cD = 512;
constexpr int cH = 2048;
constexpr int cL = 4;
constexpr int cV = 32000;
constexpr int cM = cB * cS;  // 4096 rows

// ---------------- static device scratch (no allocation allowed) -------------
__device__ float gX [cM * cD];   // residual stream
__device__ float gHn[cM * cD];   // decay-normed x
__device__ float gQ [cM * cD];   // quantity proj
__device__ float gO [cM * cD];   // attention out
__device__ float gT1[cM * cD];   // silu(out) @ Wo^T
__device__ float gG1[cM * cD];   // gate proj
__device__ float gF [cM * cD];   // ffn-normed / out-normed
__device__ float gFH[cM * cH];
__device__ float gFG[cM * cH];
__device__ float gNL[cM];        // log-sigmoid lambda per (b,s)

// ---------------------------------------------------------------------------
// Embedding gather: X[row, :] = emb[tokens[row], :]
__global__ void embed_k(const int* __restrict__ tok,
                        const float* __restrict__ emb,
                        float* __restrict__ x) {
    int i = blockIdx.x * blockDim.x + threadIdx.x;   // over cM*cD/4 float4s
    int row = i / (cD / 4);
    int c   = i % (cD / 4);
    int t = tok[row];
    ((float4*)x)[i] = ((const float4*)(emb + (size_t)t * cD))[c];
}

// ---------------------------------------------------------------------------
// RMSNorm over D=512. 128 threads/row, 1 float4 per thread.
__global__ void rmsnorm_k(const float* __restrict__ x,
                          const float* __restrict__ w,
                          float* __restrict__ y) {
    int row = blockIdx.x;
    int tid = threadIdx.x;
    const float* xr = x + (size_t)row * cD;
    float4 v = ((const float4*)xr)[tid];
    float ss = v.x * v.x + v.y * v.y + v.z * v.z + v.w * v.w;
    #pragma unroll
    for (int o = 16; o; o >>= 1) ss += __shfl_xor_sync(0xFFFFFFFFu, ss, o);
    __shared__ float sred[4];
    if ((tid & 31) == 0) sred[tid >> 5] = ss;
    __syncthreads();
    float tot = sred[0] + sred[1] + sred[2] + sred[3];
    float sc = rsqrtf(tot * (1.0f / cD) + 1e-6f);
    float4 wv = ((const float4*)w)[tid];
    float4 o4;
    o4.x = v.x * sc * wv.x;
    o4.y = v.y * sc * wv.y;
    o4.z = v.z * sc * wv.z;
    o4.w = v.w * sc * wv.w;
    ((float4*)(y + (size_t)row * cD))[tid] = o4;
}

// ---------------------------------------------------------------------------
// nl[row] = log_sigmoid( dot(h[row,:], lambda_w[:]) )
__global__ void lambda_k(const float* __restrict__ h,
                         const float* __restrict__ lw,
                         float* __restrict__ nlout) {
    int row = blockIdx.x;
    int tid = threadIdx.x;
    float4 hv = ((const float4*)(h + (size_t)row * cD))[tid];
    float4 lv = ((const float4*)lw)[tid];
    float d = hv.x * lv.x + hv.y * lv.y + hv.z * lv.z + hv.w * lv.w;
    #pragma unroll
    for (int o = 16; o; o >>= 1) d += __shfl_xor_sync(0xFFFFFFFFu, d, o);
    __shared__ float sred[4];
    if ((tid & 31) == 0) sred[tid >> 5] = d;
    __syncthreads();
    if (tid == 0) {
        float z = sred[0] + sred[1] + sred[2] + sred[3];
        float nl = (z >= 0.f) ? -log1pf(expf(-z)) : (z - log1pf(expf(z)));
        nlout[row] = nl;
    }
}

// ---------------------------------------------------------------------------
// Windowed decay attention: O[b,s,d] = sum_{t<=s} exp(nl[b,t]*(s-t)) * Q[b,t,d]
// Block: 64 s-rows x 64 d-cols, 256 threads, 4x4 microtile.
// Weights are a function of (s,t) only -> computed once into SMEM, shared
// across the 64 d-columns. Tiles whose max weight < 1e-12 are skipped; the
// t-range is capped at a 1024 window (decay rates make older keys underflow).
__global__ void __launch_bounds__(256) attn_k(const float* __restrict__ Q,
                                              const float* __restrict__ NL,
                                              float* __restrict__ O) {
    __shared__ float q_sm[16][64];
    __shared__ float w_sm[16][64];
    __shared__ float nl_sm[16];

    int b  = blockIdx.z;
    int s0 = blockIdx.y * 64;
    int d0 = blockIdx.x * 64;
    int tid = threadIdx.x;
    int tx = tid & 15;   // d group -> d = d0 + tx*4 + j
    int ty = tid >> 4;   // s group -> s = s0 + ty*4 + i

    float acc[4][4] = {};
    const float* Qb  = Q  + (size_t)b * cS * cD;
    const float* NLb = NL + (size_t)b * cS;

    int t_lo = s0 - 1024; if (t_lo < 0) t_lo = 0;
    int t_hi = s0 + 63;

    for (int t0 = t_lo; t0 <= t_hi; t0 += 16) {
        // liveness test on this 16-key tile (max weight over tile)
        int pred = 0;
        if (tid < 16) {
            int t = t0 + tid;
            if (t <= t_hi) {
                float nlv = NLb[t < cS ? t : (cS - 1)];
                nl_sm[tid] = nlv;
                int gap = s0 - t; if (gap < 0) gap = 0;
                pred = (nlv * (float)gap > -27.6f);
            }
        }
        int alive = __syncthreads_count(pred);   // barrier + reduce
        if (alive == 0) continue;

        // stage q tile [16 keys x 64 dims]
        {
            int k  = tid >> 4;
            int dc = (tid & 15) << 2;
            int t = t0 + k; if (t > cS - 1) t = cS - 1;  // weights are 0 there
            float4 qv = *(const float4*)(Qb + (size_t)t * cD + d0 + dc);
            *(float4*)&q_sm[k][dc] = qv;
        }
        // stage weights [16 keys x 64 queries]
        #pragma unroll
        for (int j = 0; j < 4; j++) {
            int idx = tid + j * 256;
            int k  = idx >> 6;
            int sl = idx & 63;
            int t = t0 + k, s = s0 + sl;
            float w = 0.f;
            if (t <= s) w = __expf(nl_sm[k] * (float)(s - t));
            w_sm[k][sl] = w;
        }
        __syncthreads();

        #pragma unroll
        for (int k = 0; k < 16; k++) {
            float4 qv = *(const float4*)&q_sm[k][tx * 4];
            float wv0 = w_sm[k][ty * 4 + 0];
            float wv1 = w_sm[k][ty * 4 + 1];
            float wv2 = w_sm[k][ty * 4 + 2];
            float wv3 = w_sm[k][ty * 4 + 3];
            acc[0][0] += wv0 * qv.x; acc[0][1] += wv0 * qv.y; acc[0][2] += wv0 * qv.z; acc[0][3] += wv0 * qv.w;
            acc[1][0] += wv1 * qv.x; acc[1][1] += wv1 * qv.y; acc[1][2] += wv1 * qv.z; acc[1][3] += wv1 * qv.w;
            acc[2][0] += wv2 * qv.x; acc[2][1] += wv2 * qv.y; acc[2][2] += wv2 * qv.z; acc[2][3] += wv2 * qv.w;
            acc[3][0] += wv3 * qv.x; acc[3][1] += wv3 * qv.y; acc[3][2] += wv3 * qv.z; acc[3][3] += wv3 * qv.w;
        }
        __syncthreads();
    }

    #pragma unroll
    for (int i = 0; i < 4; i++) {
        float4 o4;
        o4.x = acc[i][0]; o4.y = acc[i][1]; o4.z = acc[i][2]; o4.w = acc[i][3];
        *(float4*)(O + (size_t)(b * cS + s0 + ty * 4 + i) * cD + d0 + tx * 4) = o4;
    }
}

// ---------------------------------------------------------------------------
// NT SGEMM: C[M,N] = A[M,K] @ W[N,K]^T  (both row-major, K contiguous)
// 128x128 tile, BK=16, 256 threads, 8x8 microtile. BETA=1 -> C += result.
// All shapes here are multiples of (128, 128, 16): no bounds checks.
template<int BETA>
__global__ void __launch_bounds__(256) gemm_nt(const float* __restrict__ A,
                                               const float* __restrict__ Wn,
                                               float* __restrict__ C,
                                               int Mdim, int Ndim, int Kdim) {
    __shared__ float As[16][132];
    __shared__ float Bs[16][132];
    int tid = threadIdx.x;
    int tx = tid & 15, ty = tid >> 4;
    int m0 = blockIdx.y * 128, n0 = blockIdx.x * 128;
    const float* Ab = A  + (size_t)m0 * Kdim;
    const float* Bb = Wn + (size_t)n0 * Kdim;
    float acc[8][8] = {};

    for (int kt = 0; kt < Kdim; kt += 16) {
        __syncthreads();
        #pragma unroll
        for (int i = 0; i < 2; i++) {
            int id = tid + i * 256;
            int r = id >> 2, kc = (id & 3) << 2;
            float4 a = *(const float4*)(Ab + (size_t)r * Kdim + kt + kc);
            As[kc + 0][r] = a.x; As[kc + 1][r] = a.y; As[kc + 2][r] = a.z; As[kc + 3][r] = a.w;
            float4 bV = *(const float4*)(Bb + (size_t)r * Kdim + kt + kc);
            Bs[kc + 0][r] = bV.x; Bs[kc + 1][r] = bV.y; Bs[kc + 2][r] = bV.z; Bs[kc + 3][r] = bV.w;
        }
        __syncthreads();
        #pragma unroll
        for (int k = 0; k < 16; k++) {
            float a[8], bq[8];
            *(float4*)(a)      = *(const float4*)&As[k][ty * 8];
            *(float4*)(a + 4)  = *(const float4*)&As[k][ty * 8 + 4];
            *(float4*)(bq)     = *(const float4*)&Bs[k][tx * 8];
            *(float4*)(bq + 4) = *(const float4*)&Bs[k][tx * 8 + 4];
            #pragma unroll
            for (int i = 0; i < 8; i++)
                #pragma unroll
                for (int j = 0; j < 8; j++)
                    acc[i][j] += a[i] * bq[j];
        }
    }

    #pragma unroll
    for (int i = 0; i < 8; i++) {
        float* Cr = C + (size_t)(m0 + ty * 8 + i) * Ndim + n0 + tx * 8;
        if (BETA) {
            #pragma unroll
            for (int j = 0; j < 8; j++) Cr[j] += acc[i][j];
        } else {
            float4 v0, v1;
            v0.x = acc[i][0]; v0.y = acc[i][1]; v0.z = acc[i][2]; v0.w = acc[i][3];
            v1.x = acc[i][4]; v1.y = acc[i][5]; v1.z = acc[i][6]; v1.w = acc[i][7];
            *(float4*)(Cr)     = v0;
            *(float4*)(Cr + 4) = v1;
        }
    }
}

// ---------------------------------------------------------------------------
// Elementwise ops (all sizes are multiples of 1024 float4s)
__global__ void silu_k(float* __restrict__ x) {
    int i = blockIdx.x * blockDim.x + threadIdx.x;
    float4 v = ((float4*)x)[i];
    v.x = v.x / (1.f + expf(-v.x));
    v.y = v.y / (1.f + expf(-v.y));
    v.z = v.z / (1.f + expf(-v.z));
    v.w = v.w / (1.f + expf(-v.w));
    ((float4*)x)[i] = v;
}

__global__ void addmul_k(float* __restrict__ x, const float* __restrict__ a,
                         const float* __restrict__ b) {
    int i = blockIdx.x * blockDim.x + threadIdx.x;
    float4 xv = ((float4*)x)[i];
    float4 av = ((const float4*)a)[i];
    float4 bv = ((const float4*)b)[i];
    xv.x += av.x * bv.x; xv.y += av.y * bv.y;
    xv.z += av.z * bv.z; xv.w += av.w * bv.w;
    ((float4*)x)[i] = xv;
}

__global__ void mulsilu_k(float* __restrict__ h, const float* __restrict__ g) {
    int i = blockIdx.x * blockDim.x + threadIdx.x;
    float4 hv = ((float4*)h)[i];
    float4 gv = ((const float4*)g)[i];
    hv.x *= gv.x / (1.f + expf(-gv.x));
    hv.y *= gv.y / (1.f + expf(-gv.y));
    hv.z *= gv.z / (1.f + expf(-gv.z));
    hv.w *= gv.w / (1.f + expf(-gv.w));
    ((float4*)h)[i] = hv;
}

// ---------------------------------------------------------------------------
extern "C" void kernel_launch(void* const* d_in, const int* in_sizes, int n_in,
                              void* d_out, int out_size) {
    const int*   tokens       = (const int*)  d_in[0];
    const float* emb          = (const float*)d_in[1];
    const float* decay_norm_w = (const float*)d_in[2];
    const float* lambda_w     = (const float*)d_in[3];
    const float* quantity_w   = (const float*)d_in[4];
    const float* gate_w       = (const float*)d_in[5];
    const float* output_w     = (const float*)d_in[6];
    const float* ffn_norm_w   = (const float*)d_in[7];
    const float* w_h          = (const float*)d_in[8];
    const float* w_g          = (const float*)d_in[9];
    const float* w_o          = (const float*)d_in[10];
    const float* out_norm_w   = (const float*)d_in[11];
    float* out = (float*)d_out;

    float *X, *H, *Q, *O, *T1, *G1, *F, *FH, *FG, *NL;
    cudaGetSymbolAddress((void**)&X,  gX);
    cudaGetSymbolAddress((void**)&H,  gHn);
    cudaGetSymbolAddress((void**)&Q,  gQ);
    cudaGetSymbolAddress((void**)&O,  gO);
    cudaGetSymbolAddress((void**)&T1, gT1);
    cudaGetSymbolAddress((void**)&G1, gG1);
    cudaGetSymbolAddress((void**)&F,  gF);
    cudaGetSymbolAddress((void**)&FH, gFH);
    cudaGetSymbolAddress((void**)&FG, gFG);
    cudaGetSymbolAddress((void**)&NL, gNL);

    const int EW_D = (cM * cD / 4) / 256;   // 2048 blocks for D-sized arrays
    const int EW_H = (cM * cH / 4) / 256;   // 8192 blocks for HID-sized arrays

    embed_k<<<EW_D, 256>>>(tokens, emb, X);

    for (int l = 0; l < cL; l++) {
        rmsnorm_k<<<cM, 128>>>(X, decay_norm_w + (size_t)l * cD, H);
        lambda_k <<<cM, 128>>>(H, lambda_w + (size_t)l * cD, NL);
        gemm_nt<0><<<dim3(cD / 128, cM / 128), 256>>>(
            H, quantity_w + (size_t)l * cD * cD, Q, cM, cD, cD);
        attn_k<<<dim3(cD / 64, cS / 64, cB), 256>>>(Q, NL, O);
        silu_k<<<EW_D, 256>>>(O);
        gemm_nt<0><<<dim3(cD / 128, cM / 128), 256>>>(
            O, output_w + (size_t)l * cD * cD, T1, cM, cD, cD);
        gemm_nt<0><<<dim3(cD / 128, cM / 128), 256>>>(
            H, gate_w + (size_t)l * cD * cD, G1, cM, cD, cD);
        addmul_k<<<EW_D, 256>>>(X, T1, G1);
        rmsnorm_k<<<cM, 128>>>(X, ffn_norm_w + (size_t)l * cD, F);
        gemm_nt<0><<<dim3(cH / 128, cM / 128), 256>>>(
            F, w_h + (size_t)l * cH * cD, FH, cM, cH, cD);
        gemm_nt<0><<<dim3(cH / 128, cM / 128), 256>>>(
            F, w_g + (size_t)l * cH * cD, FG, cM, cH, cD);
        mulsilu_k<<<EW_H, 256>>>(FH, FG);
        gemm_nt<1><<<dim3(cD / 128, cM / 128), 256>>>(
            FH, w_o + (size_t)l * cD * cH, X, cM, cD, cH);
    }

    rmsnorm_k<<<cM, 128>>>(X, out_norm_w, F);
    gemm_nt<0><<<dim3(cV / 128, cM / 128), 256>>>(F, emb, out, cM, cV, cD);
}

// round 3
// speedup vs baseline: 2.2191x; 2.2191x over previous
#include <cuda_runtime.h>
#include <cuda_bf16.h>
#include <cstdint>
#include <math.h>

// Problem constants
constexpr int cB = 2;
constexpr int cS = 2048;
constexpr int cD = 512;
constexpr int cH = 2048;
constexpr int cL = 4;
constexpr int cV = 32000;
constexpr int cM = cB * cS;  // 4096 rows

// ---------------- static device scratch (no allocation allowed) -------------
__device__ float gX [cM * cD];
__device__ float gHn[cM * cD];
__device__ float gQ [cM * cD];
__device__ float gO [cM * cD];
__device__ float gT1[cM * cD];
__device__ float gG1[cM * cD];
__device__ float gF [cM * cD];
__device__ float gFH[cM * cH];
__device__ float gFG[cM * cH];
__device__ float gNL[cM];

// bf16 hi/lo split buffers
constexpr size_t W_EMB_OFF = 0;
constexpr size_t W_EMB_SZ  = (size_t)cV * cD;
constexpr size_t W_LAYER_SZ = 3 * (size_t)cD * cD + 2 * (size_t)cH * cD + (size_t)cD * cH;
constexpr size_t W_TOTAL   = W_EMB_SZ + cL * W_LAYER_SZ;

__device__ __nv_bfloat16 gWhi[W_TOTAL];
__device__ __nv_bfloat16 gWlo[W_TOTAL];
__device__ __nv_bfloat16 gAhi[(size_t)cM * cH];
__device__ __nv_bfloat16 gAlo[(size_t)cM * cH];

// ============================ PTX helpers ===================================
__device__ __forceinline__ uint32_t smem_u32(const void* p) {
    uint32_t a;
    asm("{ .reg .u64 t; cvta.to.shared.u64 t, %1; cvt.u32.u64 %0, t; }"
        : "=r"(a) : "l"(p));
    return a;
}

__device__ __forceinline__ void cp16(uint32_t dst, const void* src) {
    asm volatile("cp.async.cg.shared.global [%0], [%1], 16;" :: "r"(dst), "l"(src));
}
#define CP_COMMIT() asm volatile("cp.async.commit_group;" ::: "memory")
#define CP_WAIT(n)  asm volatile("cp.async.wait_group %0;" :: "n"(n) : "memory")

__device__ __forceinline__ void ldsm4(uint32_t* r, uint32_t addr) {
    asm volatile("ldmatrix.sync.aligned.m8n8.x4.shared.b16 {%0,%1,%2,%3}, [%4];"
        : "=r"(r[0]), "=r"(r[1]), "=r"(r[2]), "=r"(r[3]) : "r"(addr));
}

__device__ __forceinline__ void mma16816(float* c, const uint32_t* a, const uint32_t* b) {
    asm volatile(
        "mma.sync.aligned.m16n8k16.row.col.f32.bf16.bf16.f32 "
        "{%0,%1,%2,%3}, {%4,%5,%6,%7}, {%8,%9}, {%0,%1,%2,%3};"
        : "+f"(c[0]), "+f"(c[1]), "+f"(c[2]), "+f"(c[3])
        : "r"(a[0]), "r"(a[1]), "r"(a[2]), "r"(a[3]), "r"(b[0]), "r"(b[1]));
}

// ---------------------------------------------------------------------------
// fp32 -> bf16 hi/lo split conversion. n4 = elems/4.
__global__ void cvt_k(const float* __restrict__ s,
                      __nv_bfloat16* __restrict__ hi,
                      __nv_bfloat16* __restrict__ lo, int n4) {
    int i = blockIdx.x * blockDim.x + threadIdx.x;
    if (i >= n4) return;
    float4 v = ((const float4*)s)[i];
    __nv_bfloat16 hx = __float2bfloat16_rn(v.x);
    __nv_bfloat16 hy = __float2bfloat16_rn(v.y);
    __nv_bfloat16 hz = __float2bfloat16_rn(v.z);
    __nv_bfloat16 hw = __float2bfloat16_rn(v.w);
    __nv_bfloat16 lx = __float2bfloat16_rn(v.x - __bfloat162float(hx));
    __nv_bfloat16 ly = __float2bfloat16_rn(v.y - __bfloat162float(hy));
    __nv_bfloat16 lz = __float2bfloat16_rn(v.z - __bfloat162float(hz));
    __nv_bfloat16 lw2 = __float2bfloat16_rn(v.w - __bfloat162float(hw));
    __nv_bfloat162* H = (__nv_bfloat162*)hi;
    __nv_bfloat162* L = (__nv_bfloat162*)lo;
    H[2 * i]     = __nv_bfloat162(hx, hy);
    H[2 * i + 1] = __nv_bfloat162(hz, hw);
    L[2 * i]     = __nv_bfloat162(lx, ly);
    L[2 * i + 1] = __nv_bfloat162(lz, lw2);
}

// ---------------------------------------------------------------------------
// mma.sync NT GEMM: C[M,N] (+)= A[M,K] @ B[N,K]^T with bf16x3 splitting.
// CTA tile 128x64, 8 warps (warp tile 32x32), K-chunk 32, cp.async double buf.
// SMEM rows padded to 40 bf16 (5 x 16B units, coprime 8 -> conflict-free LDSM).
constexpr int PAD = 40;
constexpr int OFF_AHI = 0;
constexpr int OFF_ALO = 128 * PAD;
constexpr int OFF_BHI = 256 * PAD;
constexpr int OFF_BLO = 256 * PAD + 64 * PAD;
constexpr int BUF_ELEMS = (256 + 128) * PAD;        // 15360 bf16
constexpr int BUF_BYTES = BUF_ELEMS * 2;            // 30720
constexpr int GSMEM = 2 * BUF_BYTES;                // 61440

__device__ __forceinline__ void stage_chunk(
    const __nv_bfloat16* __restrict__ Ahi, const __nv_bfloat16* __restrict__ Alo,
    const __nv_bfloat16* __restrict__ Bhi, const __nv_bfloat16* __restrict__ Blo,
    int m0, int n0, int Kdim, int kt, uint32_t sbuf, int tid) {
    #pragma unroll
    for (int it = 0; it < 2; it++) {
        int i = tid + it * 256;
        int r = i >> 2, c = (i & 3) << 3;
        size_t g = (size_t)(m0 + r) * Kdim + kt + c;
        uint32_t d = sbuf + (uint32_t)(r * PAD + c) * 2;
        cp16(d + OFF_AHI * 2, Ahi + g);
        cp16(d + OFF_ALO * 2, Alo + g);
    }
    {
        int r = tid >> 2, c = (tid & 3) << 3;
        size_t g = (size_t)(n0 + r) * Kdim + kt + c;
        uint32_t d = sbuf + (uint32_t)(r * PAD + c) * 2;
        cp16(d + OFF_BHI * 2, Bhi + g);
        cp16(d + OFF_BLO * 2, Blo + g);
    }
}

template<int BETA>
__global__ void __launch_bounds__(256) gemm_mma(
    const __nv_bfloat16* __restrict__ Ahi, const __nv_bfloat16* __restrict__ Alo,
    const __nv_bfloat16* __restrict__ Bhi, const __nv_bfloat16* __restrict__ Blo,
    float* __restrict__ C, int Ndim, int Kdim) {
    extern __shared__ char smc[];
    const uint32_t sbase = smem_u32(smc);
    const int tid = threadIdx.x;
    const int lane = tid & 31, wid = tid >> 5;
    const int wm = wid & 3, wn = wid >> 2;
    const int m0 = blockIdx.y * 128, n0 = blockIdx.x * 64;
    const int NC = Kdim >> 5;

    float acc[2][4][4] = {};

    // per-lane ldmatrix address components (bf16-element offsets *2 = bytes)
    const uint32_t a_lane = (uint32_t)((lane & 15) * PAD + ((lane >> 4) << 3)) * 2;
    const uint32_t b_lane = (uint32_t)(((lane & 7) + ((lane >> 4) << 3)) * PAD
                                       + (((lane >> 3) & 1) << 3)) * 2;

    stage_chunk(Ahi, Alo, Bhi, Blo, m0, n0, Kdim, 0, sbase, tid);
    CP_COMMIT();

    for (int c = 0; c < NC; c++) {
        const int buf = c & 1;
        if (c + 1 < NC) {
            stage_chunk(Ahi, Alo, Bhi, Blo, m0, n0, Kdim, (c + 1) << 5,
                        sbase + (buf ^ 1) * BUF_BYTES, tid);
            CP_COMMIT();
            CP_WAIT(1);
        } else {
            CP_WAIT(0);
        }
        __syncthreads();

        const uint32_t sb = sbase + buf * BUF_BYTES;
        #pragma unroll
        for (int ks = 0; ks < 32; ks += 16) {
            uint32_t ah[2][4], al[2][4], bh[2][4], bl[2][4];
            #pragma unroll
            for (int mt = 0; mt < 2; mt++) {
                uint32_t ar = sb + (uint32_t)(((wm * 32 + mt * 16) * PAD + ks) * 2) + a_lane;
                ldsm4(ah[mt], ar + OFF_AHI * 2);
                ldsm4(al[mt], ar + OFF_ALO * 2);
            }
            #pragma unroll
            for (int p = 0; p < 2; p++) {
                uint32_t br = sb + (uint32_t)(((wn * 32 + p * 16) * PAD + ks) * 2) + b_lane;
                ldsm4(bh[p], br + OFF_BHI * 2);
                ldsm4(bl[p], br + OFF_BLO * 2);
            }
            #pragma unroll
            for (int mt = 0; mt < 2; mt++)
                #pragma unroll
                for (int nt = 0; nt < 4; nt++) {
                    const uint32_t* bhp = &bh[nt >> 1][(nt & 1) * 2];
                    const uint32_t* blp = &bl[nt >> 1][(nt & 1) * 2];
                    mma16816(acc[mt][nt], ah[mt], bhp);
                    mma16816(acc[mt][nt], ah[mt], blp);
                    mma16816(acc[mt][nt], al[mt], bhp);
                }
        }
        __syncthreads();
    }

    // epilogue
    #pragma unroll
    for (int mt = 0; mt < 2; mt++) {
        int row = m0 + wm * 32 + mt * 16 + (lane >> 2);
        #pragma unroll
        for (int nt = 0; nt < 4; nt++) {
            int col = n0 + wn * 32 + nt * 8 + (lane & 3) * 2;
            float* c0 = C + (size_t)row * Ndim + col;
            float* c1 = C + (size_t)(row + 8) * Ndim + col;
            if (BETA) {
                c0[0] += acc[mt][nt][0]; c0[1] += acc[mt][nt][1];
                c1[0] += acc[mt][nt][2]; c1[1] += acc[mt][nt][3];
            } else {
                *(float2*)c0 = make_float2(acc[mt][nt][0], acc[mt][nt][1]);
                *(float2*)c1 = make_float2(acc[mt][nt][2], acc[mt][nt][3]);
            }
        }
    }
}

// ---------------------------------------------------------------------------
// Embedding gather
__global__ void embed_k(const int* __restrict__ tok,
                        const float* __restrict__ emb,
                        float* __restrict__ x) {
    int i = blockIdx.x * blockDim.x + threadIdx.x;
    int row = i / (cD / 4);
    int c   = i % (cD / 4);
    int t = tok[row];
    ((float4*)x)[i] = ((const float4*)(emb + (size_t)t * cD))[c];
}

// RMSNorm over D=512. 128 threads/row.
__global__ void rmsnorm_k(const float* __restrict__ x,
                          const float* __restrict__ w,
                          float* __restrict__ y) {
    int row = blockIdx.x;
    int tid = threadIdx.x;
    const float* xr = x + (size_t)row * cD;
    float4 v = ((const float4*)xr)[tid];
    float ss = v.x * v.x + v.y * v.y + v.z * v.z + v.w * v.w;
    #pragma unroll
    for (int o = 16; o; o >>= 1) ss += __shfl_xor_sync(0xFFFFFFFFu, ss, o);
    __shared__ float sred[4];
    if ((tid & 31) == 0) sred[tid >> 5] = ss;
    __syncthreads();
    float tot = sred[0] + sred[1] + sred[2] + sred[3];
    float sc = rsqrtf(tot * (1.0f / cD) + 1e-6f);
    float4 wv = ((const float4*)w)[tid];
    float4 o4;
    o4.x = v.x * sc * wv.x;
    o4.y = v.y * sc * wv.y;
    o4.z = v.z * sc * wv.z;
    o4.w = v.w * sc * wv.w;
    ((float4*)(y + (size_t)row * cD))[tid] = o4;
}

// nl[row] = log_sigmoid( dot(h[row,:], lambda_w[:]) )
__global__ void lambda_k(const float* __restrict__ h,
                         const float* __restrict__ lw,
                         float* __restrict__ nlout) {
    int row = blockIdx.x;
    int tid = threadIdx.x;
    float4 hv = ((const float4*)(h + (size_t)row * cD))[tid];
    float4 lv = ((const float4*)lw)[tid];
    float d = hv.x * lv.x + hv.y * lv.y + hv.z * lv.z + hv.w * lv.w;
    #pragma unroll
    for (int o = 16; o; o >>= 1) d += __shfl_xor_sync(0xFFFFFFFFu, d, o);
    __shared__ float sred[4];
    if ((tid & 31) == 0) sred[tid >> 5] = d;
    __syncthreads();
    if (tid == 0) {
        float z = sred[0] + sred[1] + sred[2] + sred[3];
        float nl = (z >= 0.f) ? -log1pf(expf(-z)) : (z - log1pf(expf(z)));
        nlout[row] = nl;
    }
}

// Windowed decay attention (weights underflow past ~1024 keys)
__global__ void __launch_bounds__(256) attn_k(const float* __restrict__ Q,
                                              const float* __restrict__ NL,
                                              float* __restrict__ O) {
    __shared__ float q_sm[16][64];
    __shared__ float w_sm[16][64];
    __shared__ float nl_sm[16];

    int b  = blockIdx.z;
    int s0 = blockIdx.y * 64;
    int d0 = blockIdx.x * 64;
    int tid = threadIdx.x;
    int tx = tid & 15;
    int ty = tid >> 4;

    float acc[4][4] = {};
    const float* Qb  = Q  + (size_t)b * cS * cD;
    const float* NLb = NL + (size_t)b * cS;

    int t_lo = s0 - 1024; if (t_lo < 0) t_lo = 0;
    int t_hi = s0 + 63;

    for (int t0 = t_lo; t0 <= t_hi; t0 += 16) {
        int pred = 0;
        if (tid < 16) {
            int t = t0 + tid;
            if (t <= t_hi) {
                float nlv = NLb[t < cS ? t : (cS - 1)];
                nl_sm[tid] = nlv;
                int gap = s0 - t; if (gap < 0) gap = 0;
                pred = (nlv * (float)gap > -27.6f);
            }
        }
        int alive = __syncthreads_count(pred);
        if (alive == 0) continue;

        {
            int k  = tid >> 4;
            int dc = (tid & 15) << 2;
            int t = t0 + k; if (t > cS - 1) t = cS - 1;
            float4 qv = *(const float4*)(Qb + (size_t)t * cD + d0 + dc);
            *(float4*)&q_sm[k][dc] = qv;
        }
        #pragma unroll
        for (int j = 0; j < 4; j++) {
            int idx = tid + j * 256;
            int k  = idx >> 6;
            int sl = idx & 63;
            int t = t0 + k, s = s0 + sl;
            float w = 0.f;
            if (t <= s) w = __expf(nl_sm[k] * (float)(s - t));
            w_sm[k][sl] = w;
        }
        __syncthreads();

        #pragma unroll
        for (int k = 0; k < 16; k++) {
            float4 qv = *(const float4*)&q_sm[k][tx * 4];
            float wv0 = w_sm[k][ty * 4 + 0];
            float wv1 = w_sm[k][ty * 4 + 1];
            float wv2 = w_sm[k][ty * 4 + 2];
            float wv3 = w_sm[k][ty * 4 + 3];
            acc[0][0] += wv0 * qv.x; acc[0][1] += wv0 * qv.y; acc[0][2] += wv0 * qv.z; acc[0][3] += wv0 * qv.w;
            acc[1][0] += wv1 * qv.x; acc[1][1] += wv1 * qv.y; acc[1][2] += wv1 * qv.z; acc[1][3] += wv1 * qv.w;
            acc[2][0] += wv2 * qv.x; acc[2][1] += wv2 * qv.y; acc[2][2] += wv2 * qv.z; acc[2][3] += wv2 * qv.w;
            acc[3][0] += wv3 * qv.x; acc[3][1] += wv3 * qv.y; acc[3][2] += wv3 * qv.z; acc[3][3] += wv3 * qv.w;
        }
        __syncthreads();
    }

    #pragma unroll
    for (int i = 0; i < 4; i++) {
        float4 o4;
        o4.x = acc[i][0]; o4.y = acc[i][1]; o4.z = acc[i][2]; o4.w = acc[i][3];
        *(float4*)(O + (size_t)(b * cS + s0 + ty * 4 + i) * cD + d0 + tx * 4) = o4;
    }
}

// Elementwise ops
__global__ void silu_k(float* __restrict__ x) {
    int i = blockIdx.x * blockDim.x + threadIdx.x;
    float4 v = ((float4*)x)[i];
    v.x = v.x / (1.f + expf(-v.x));
    v.y = v.y / (1.f + expf(-v.y));
    v.z = v.z / (1.f + expf(-v.z));
    v.w = v.w / (1.f + expf(-v.w));
    ((float4*)x)[i] = v;
}

__global__ void addmul_k(float* __restrict__ x, const float* __restrict__ a,
                         const float* __restrict__ b) {
    int i = blockIdx.x * blockDim.x + threadIdx.x;
    float4 xv = ((float4*)x)[i];
    float4 av = ((const float4*)a)[i];
    float4 bv = ((const float4*)b)[i];
    xv.x += av.x * bv.x; xv.y += av.y * bv.y;
    xv.z += av.z * bv.z; xv.w += av.w * bv.w;
    ((float4*)x)[i] = xv;
}

__global__ void mulsilu_k(float* __restrict__ h, const float* __restrict__ g) {
    int i = blockIdx.x * blockDim.x + threadIdx.x;
    float4 hv = ((float4*)h)[i];
    float4 gv = ((const float4*)g)[i];
    hv.x *= gv.x / (1.f + expf(-gv.x));
    hv.y *= gv.y / (1.f + expf(-gv.y));
    hv.z *= gv.z / (1.f + expf(-gv.z));
    hv.w *= gv.w / (1.f + expf(-gv.w));
    ((float4*)h)[i] = hv;
}

// ---------------------------------------------------------------------------
extern "C" void kernel_launch(void* const* d_in, const int* in_sizes, int n_in,
                              void* d_out, int out_size) {
    const int*   tokens       = (const int*)  d_in[0];
    const float* emb          = (const float*)d_in[1];
    const float* decay_norm_w = (const float*)d_in[2];
    const float* lambda_w     = (const float*)d_in[3];
    const float* quantity_w   = (const float*)d_in[4];
    const float* gate_w       = (const float*)d_in[5];
    const float* output_w     = (const float*)d_in[6];
    const float* ffn_norm_w   = (const float*)d_in[7];
    const float* w_h          = (const float*)d_in[8];
    const float* w_g          = (const float*)d_in[9];
    const float* w_o          = (const float*)d_in[10];
    const float* out_norm_w   = (const float*)d_in[11];
    float* out = (float*)d_out;

    float *X, *H, *Q, *O, *T1, *G1, *F, *FH, *FG, *NL;
    cudaGetSymbolAddress((void**)&X,  gX);
    cudaGetSymbolAddress((void**)&H,  gHn);
    cudaGetSymbolAddress((void**)&Q,  gQ);
    cudaGetSymbolAddress((void**)&O,  gO);
    cudaGetSymbolAddress((void**)&T1, gT1);
    cudaGetSymbolAddress((void**)&G1, gG1);
    cudaGetSymbolAddress((void**)&F,  gF);
    cudaGetSymbolAddress((void**)&FH, gFH);
    cudaGetSymbolAddress((void**)&FG, gFG);
    cudaGetSymbolAddress((void**)&NL, gNL);
    __nv_bfloat16 *Whi, *Wlo, *Ahi, *Alo;
    cudaGetSymbolAddress((void**)&Whi, gWhi);
    cudaGetSymbolAddress((void**)&Wlo, gWlo);
    cudaGetSymbolAddress((void**)&Ahi, gAhi);
    cudaGetSymbolAddress((void**)&Alo, gAlo);

    static bool attr_set = false;
    if (!attr_set) {
        cudaFuncSetAttribute(gemm_mma<0>, cudaFuncAttributeMaxDynamicSharedMemorySize, GSMEM);
        cudaFuncSetAttribute(gemm_mma<1>, cudaFuncAttributeMaxDynamicSharedMemorySize, GSMEM);
        attr_set = true;
    }

    // ---- weight conversion to bf16 hi/lo --------------------------------
    auto cvt = [](const float* s, __nv_bfloat16* h, __nv_bfloat16* l, size_t n) {
        int n4 = (int)(n / 4);
        cvt_k<<<(n4 + 255) / 256, 256>>>(s, h, l, n4);
    };
    cvt(emb, Whi + W_EMB_OFF, Wlo + W_EMB_OFF, W_EMB_SZ);
    size_t offQ[cL], offG[cL], offO[cL], offWH[cL], offWG[cL], offWO[cL];
    for (int l = 0; l < cL; l++) {
        size_t base = W_EMB_SZ + (size_t)l * W_LAYER_SZ;
        offQ[l]  = base;
        offG[l]  = base + (size_t)cD * cD;
        offO[l]  = base + 2 * (size_t)cD * cD;
        offWH[l] = base + 3 * (size_t)cD * cD;
        offWG[l] = offWH[l] + (size_t)cH * cD;
        offWO[l] = offWG[l] + (size_t)cH * cD;
        cvt(quantity_w + (size_t)l * cD * cD, Whi + offQ[l],  Wlo + offQ[l],  (size_t)cD * cD);
        cvt(gate_w     + (size_t)l * cD * cD, Whi + offG[l],  Wlo + offG[l],  (size_t)cD * cD);
        cvt(output_w   + (size_t)l * cD * cD, Whi + offO[l],  Wlo + offO[l],  (size_t)cD * cD);
        cvt(w_h        + (size_t)l * cH * cD, Whi + offWH[l], Wlo + offWH[l], (size_t)cH * cD);
        cvt(w_g        + (size_t)l * cH * cD, Whi + offWG[l], Wlo + offWG[l], (size_t)cH * cD);
        cvt(w_o        + (size_t)l * cD * cH, Whi + offWO[l], Wlo + offWO[l], (size_t)cD * cH);
    }

    const int EW_D = (cM * cD / 4) / 256;
    const int EW_H = (cM * cH / 4) / 256;

    embed_k<<<EW_D, 256>>>(tokens, emb, X);

    for (int l = 0; l < cL; l++) {
        rmsnorm_k<<<cM, 128>>>(X, decay_norm_w + (size_t)l * cD, H);
        lambda_k <<<cM, 128>>>(H, lambda_w + (size_t)l * cD, NL);
        cvt(H, Ahi, Alo, (size_t)cM * cD);
        gemm_mma<0><<<dim3(cD / 64, cM / 128), 256, GSMEM>>>(
            Ahi, Alo, Whi + offQ[l], Wlo + offQ[l], Q, cD, cD);
        gemm_mma<0><<<dim3(cD / 64, cM / 128), 256, GSMEM>>>(
            Ahi, Alo, Whi + offG[l], Wlo + offG[l], G1, cD, cD);
        attn_k<<<dim3(cD / 64, cS / 64, cB), 256>>>(Q, NL, O);
        silu_k<<<EW_D, 256>>>(O);
        cvt(O, Ahi, Alo, (size_t)cM * cD);
        gemm_mma<0><<<dim3(cD / 64, cM / 128), 256, GSMEM>>>(
            Ahi, Alo, Whi + offO[l], Wlo + offO[l], T1, cD, cD);
        addmul_k<<<EW_D, 256>>>(X, T1, G1);
        rmsnorm_k<<<cM, 128>>>(X, ffn_norm_w + (size_t)l * cD, F);
        cvt(F, Ahi, Alo, (size_t)cM * cD);
        gemm_mma<0><<<dim3(cH / 64, cM / 128), 256, GSMEM>>>(
            Ahi, Alo, Whi + offWH[l], Wlo + offWH[l], FH, cH, cD);
        gemm_mma<0><<<dim3(cH / 64, cM / 128), 256, GSMEM>>>(
            Ahi, Alo, Whi + offWG[l], Wlo + offWG[l], FG, cH, cD);
        mulsilu_k<<<EW_H, 256>>>(FH, FG);
        cvt(FH, Ahi, Alo, (size_t)cM * cH);
        gemm_mma<1><<<dim3(cD / 64, cM / 128), 256, GSMEM>>>(
            Ahi, Alo, Whi + offWO[l], Wlo + offWO[l], X, cD, cH);
    }

    rmsnorm_k<<<cM, 128>>>(X, out_norm_w, F);
    cvt(F, Ahi, Alo, (size_t)cM * cD);
    gemm_mma<0><<<dim3(cV / 64, cM / 128), 256, GSMEM>>>(
        Ahi, Alo, Whi + W_EMB_OFF, Wlo + W_EMB_OFF, out, cV, cD);
}